// round 4
// baseline (speedup 1.0000x reference)
#include <cuda_runtime.h>

// Problem constants (fixed by setup_inputs)
#define NN    32768      // total nodes (64 * 512)
#define EE    524288     // total edges (64 * 8192)
#define BG    64         // graphs
#define NPER  512
#define EPER  8192
#define MAXA  18432      // 512*4 + 8192*2
#define EMB   128

// ---------------- scratch (device globals; no allocation allowed) ----------
__device__ float g_bufA[NN * EMB];   // GEMM outputs (pre-aggregation, inv-scaled)
__device__ float g_bufH[NN * EMB];   // post-aggregation h
__device__ float g_P[NN * EMB];      // h @ we1_top + be1
__device__ float g_Q[NN * EMB];      // h @ we1_bot
__device__ int   g_deg[NN];
__device__ int   g_off[NN + 1];
__device__ int   g_cur[NN];
__device__ int   g_col[EE];
__device__ float g_inv[NN];          // rsqrt(deg+1)
__device__ float g_pool[BG * EMB];

// ---------------- f32x2 helpers (packed fp32 FMA — 2x FFMA throughput) -----
__device__ __forceinline__ unsigned long long dup2(float a) {
    unsigned long long r;
    unsigned int ai = __float_as_uint(a);
    asm("mov.b64 %0, {%1, %1};" : "=l"(r) : "r"(ai));
    return r;
}
__device__ __forceinline__ void fma2(unsigned long long& c, unsigned long long a,
                                     unsigned long long b) {
    asm("fma.rn.f32x2 %0, %1, %2, %0;" : "+l"(c) : "l"(a), "l"(b));
}
__device__ __forceinline__ float2 unpack2(unsigned long long v) {
    unsigned int lo, hi;
    asm("mov.b64 {%0, %1}, %2;" : "=r"(lo), "=r"(hi) : "l"(v));
    return make_float2(__uint_as_float(lo), __uint_as_float(hi));
}

// ---------------- CSR build ------------------------------------------------
__global__ void hist_kernel(const int* __restrict__ ei) {
    int e = blockIdx.x * blockDim.x + threadIdx.x;
    if (e < EE) atomicAdd(&g_deg[ei[EE + e]], 1);
}

// single-block exclusive scan of g_deg (32768 values), + inv + cursor init
__global__ void scan_kernel() {
    __shared__ int s[1024];
    int t = threadIdx.x;
    int base = t * 32;
    int loc[32];
    int sum = 0;
#pragma unroll
    for (int i = 0; i < 32; i++) { loc[i] = g_deg[base + i]; sum += loc[i]; }
    s[t] = sum;
    __syncthreads();
    for (int d = 1; d < 1024; d <<= 1) {
        int tmp = (t >= d) ? s[t - d] : 0;
        __syncthreads();
        if (t >= d) s[t] += tmp;
        __syncthreads();
    }
    int run = s[t] - sum;  // exclusive prefix
#pragma unroll
    for (int i = 0; i < 32; i++) {
        g_off[base + i] = run;
        g_cur[base + i] = run;
        g_inv[base + i] = rsqrtf((float)(loc[i] + 1));  // +1 self loop
        run += loc[i];
    }
    if (t == 1023) g_off[NN] = s[1023];
}

__global__ void scatter_kernel(const int* __restrict__ ei) {
    int e = blockIdx.x * blockDim.x + threadIdx.x;
    if (e < EE) {
        int d = ei[EE + e];
        int p = atomicAdd(&g_cur[d], 1);
        g_col[p] = ei[e];
    }
}

// ---------------- GEMM: C[M=32768, 128] = A[M,K] @ B[K,128] ----------------
// EPI 0: C = acc * g_inv[row]         (GCN layer pre-scale)
// EPI 1: C = acc + bias[col]          (P head, be1 folded)
// EPI 2: C = acc                      (Q head)
// EPI 3: node head fused: t = relu(acc + bias); logits = t @ w2 + b2 -> C=d_out
template <int K, int EPI>
__global__ void __launch_bounds__(256, 1)
gemm_kernel(const float* __restrict__ A, const float* __restrict__ Bm,
            const float* __restrict__ bias, const float* __restrict__ w2,
            const float* __restrict__ b2, float* __restrict__ C) {
    extern __shared__ float smem[];
    float* As = smem;             // [K][132]  (transposed A tile, padded)
    float* Bs = smem + K * 132;   // [K][128]

    const int tid = threadIdx.x;
    const int m0 = blockIdx.x * 128;

    // load A tile (transpose into As[k][m])
    constexpr int KQ = K / 4;
    const float4* A4 = reinterpret_cast<const float4*>(A + (size_t)m0 * K);
    for (int i = tid; i < 128 * KQ; i += 256) {
        int row = i / KQ, kq = i - row * KQ;
        float4 v = A4[row * KQ + kq];
        As[(kq * 4 + 0) * 132 + row] = v.x;
        As[(kq * 4 + 1) * 132 + row] = v.y;
        As[(kq * 4 + 2) * 132 + row] = v.z;
        As[(kq * 4 + 3) * 132 + row] = v.w;
    }
    // load B (row-major copy)
    const float4* B4 = reinterpret_cast<const float4*>(Bm);
    for (int i = tid; i < K * 32; i += 256)
        reinterpret_cast<float4*>(Bs)[i] = B4[i];
    __syncthreads();

    const int tm = tid & 31;   // row quad: rows tm*4 .. tm*4+3
    const int tn = tid >> 5;   // col group: cols tn*4 + 32*q + c

    unsigned long long acc[4][4][2];
#pragma unroll
    for (int r = 0; r < 4; r++)
#pragma unroll
        for (int q = 0; q < 4; q++) { acc[r][q][0] = 0ull; acc[r][q][1] = 0ull; }

#pragma unroll 4
    for (int k = 0; k < K; k++) {
        float4 av = *reinterpret_cast<const float4*>(&As[k * 132 + tm * 4]);
        unsigned long long a0 = dup2(av.x), a1 = dup2(av.y),
                           a2 = dup2(av.z), a3 = dup2(av.w);
#pragma unroll
        for (int q = 0; q < 4; q++) {
            ulonglong2 b =
                *reinterpret_cast<const ulonglong2*>(&Bs[k * 128 + tn * 4 + 32 * q]);
            fma2(acc[0][q][0], a0, b.x); fma2(acc[0][q][1], a0, b.y);
            fma2(acc[1][q][0], a1, b.x); fma2(acc[1][q][1], a1, b.y);
            fma2(acc[2][q][0], a2, b.x); fma2(acc[2][q][1], a2, b.y);
            fma2(acc[3][q][0], a3, b.x); fma2(acc[3][q][1], a3, b.y);
        }
    }

    if constexpr (EPI == 3) __syncthreads();  // about to reuse As as Ts

    float* Ts = smem;  // [n][m] transposed hidden tile, stride 132 (EPI==3)

#pragma unroll
    for (int r = 0; r < 4; r++) {
        int mr = tm * 4 + r;
        int m = m0 + mr;
        float sc = 1.0f;
        if constexpr (EPI == 0) sc = g_inv[m];
#pragma unroll
        for (int q = 0; q < 4; q++) {
            int n0 = tn * 4 + 32 * q;
            float2 lo = unpack2(acc[r][q][0]);
            float2 hi = unpack2(acc[r][q][1]);
            float4 o = make_float4(lo.x, lo.y, hi.x, hi.y);
            if constexpr (EPI == 0) {
                o.x *= sc; o.y *= sc; o.z *= sc; o.w *= sc;
            }
            if constexpr (EPI == 1 || EPI == 3) {
                float4 bb = __ldg(&reinterpret_cast<const float4*>(bias)[tn + 8 * q]);
                o.x += bb.x; o.y += bb.y; o.z += bb.z; o.w += bb.w;
            }
            if constexpr (EPI == 3) {
                // relu, store transposed into Ts[n][m]
                Ts[(n0 + 0) * 132 + mr] = fmaxf(o.x, 0.f);
                Ts[(n0 + 1) * 132 + mr] = fmaxf(o.y, 0.f);
                Ts[(n0 + 2) * 132 + mr] = fmaxf(o.z, 0.f);
                Ts[(n0 + 3) * 132 + mr] = fmaxf(o.w, 0.f);
            } else {
                *reinterpret_cast<float4*>(&C[(size_t)m * 128 + n0]) = o;
            }
        }
    }

    if constexpr (EPI == 3) {
        __syncthreads();
        // stage 2: node_logits = t @ wn2 [128,4] + bn2, scatter into d_out
        int row = tid >> 1;          // local row 0..127
        int jj = (tid & 1) * 2;      // output pair {0,1} or {2,3}
        float s0 = 0.f, s1 = 0.f;
        const float4* W4 = reinterpret_cast<const float4*>(w2);
#pragma unroll 8
        for (int k = 0; k < 128; k++) {
            float tv = Ts[k * 132 + row];
            float4 w = __ldg(&W4[k]);  // (w[k][0..3])
            float wa = jj ? w.z : w.x;
            float wb = jj ? w.w : w.y;
            s0 += tv * wa;
            s1 += tv * wb;
        }
        int gm = m0 + row;
        int b = gm >> 9;
        int ln = gm & 511;
        float2 o2 = make_float2(s0 + b2[jj], s1 + b2[jj + 1]);
        *reinterpret_cast<float2*>(&C[(size_t)b * MAXA + ln * 4 + jj]) = o2;
    }
}

// ---------------- GCN aggregation: warp per dst node -----------------------
// h[d] = relu( inv[d] * (sum_{s in in(d)} a[s] + a[d]) + bias )
__global__ void agg_kernel(const float* __restrict__ a,
                           const float* __restrict__ bias,
                           float* __restrict__ h) {
    int wid = (blockIdx.x * blockDim.x + threadIdx.x) >> 5;
    int lane = threadIdx.x & 31;
    if (wid >= NN) return;
    const float4* A4 = reinterpret_cast<const float4*>(a);
    float4 acc = A4[wid * 32 + lane];  // self (a[d])
    int j0 = g_off[wid], j1 = g_off[wid + 1];
    for (int j = j0; j < j1; j++) {
        int s = g_col[j];
        float4 v = A4[s * 32 + lane];
        acc.x += v.x; acc.y += v.y; acc.z += v.z; acc.w += v.w;
    }
    float sc = g_inv[wid];
    float4 bv = __ldg(&reinterpret_cast<const float4*>(bias)[lane]);
    float4 o;
    o.x = fmaxf(acc.x * sc + bv.x, 0.f);
    o.y = fmaxf(acc.y * sc + bv.y, 0.f);
    o.z = fmaxf(acc.z * sc + bv.z, 0.f);
    o.w = fmaxf(acc.w * sc + bv.w, 0.f);
    reinterpret_cast<float4*>(h)[wid * 32 + lane] = o;
}

// ---------------- edge head: warp per edge ---------------------------------
// logits[b, 2048 + local_e*2 + j] = relu(P[src] + Q[dst]) . we2[:,j] + be2[j]
__global__ void edge_kernel(const int* __restrict__ ei,
                            const float* __restrict__ we2,
                            const float* __restrict__ be2,
                            float* __restrict__ out) {
    int wid = (blockIdx.x * blockDim.x + threadIdx.x) >> 5;
    int lane = threadIdx.x & 31;
    if (wid >= EE) return;
    int s = ei[wid], d = ei[EE + wid];
    const float4* P4 = reinterpret_cast<const float4*>(g_P);
    const float4* Q4 = reinterpret_cast<const float4*>(g_Q);
    float4 p = P4[s * 32 + lane];
    float4 q = Q4[d * 32 + lane];
    float t0 = fmaxf(p.x + q.x, 0.f);
    float t1 = fmaxf(p.y + q.y, 0.f);
    float t2 = fmaxf(p.z + q.z, 0.f);
    float t3 = fmaxf(p.w + q.w, 0.f);
    const float4* W = reinterpret_cast<const float4*>(we2);  // [128][2] rows paired
    float4 w0 = __ldg(&W[lane * 2]);      // rows 4l, 4l+1
    float4 w1 = __ldg(&W[lane * 2 + 1]);  // rows 4l+2, 4l+3
    float s0 = t0 * w0.x + t1 * w0.z + t2 * w1.x + t3 * w1.z;
    float s1 = t0 * w0.y + t1 * w0.w + t2 * w1.y + t3 * w1.w;
#pragma unroll
    for (int o = 16; o; o >>= 1) {
        s0 += __shfl_xor_sync(0xffffffffu, s0, o);
        s1 += __shfl_xor_sync(0xffffffffu, s1, o);
    }
    if (lane == 0) {
        int b = wid >> 13;       // edge graph = e / 8192
        int le = wid & 8191;     // local edge
        float2 o2 = make_float2(s0 + be2[0], s1 + be2[1]);
        *reinterpret_cast<float2*>(&out[(size_t)b * MAXA + 2048 + le * 2]) = o2;
    }
}

// ---------------- pooling + value head -------------------------------------
__global__ void pool_kernel(const float* __restrict__ h) {
    int b = blockIdx.x, f = threadIdx.x;  // 128 threads
    float s = 0.f;
    const float* base = h + (size_t)b * NPER * EMB + f;
#pragma unroll 8
    for (int r = 0; r < NPER; r++) s += base[r * EMB];
    g_pool[b * EMB + f] = s * (1.0f / (float)NPER);
}

__global__ void value_kernel(const float* __restrict__ wv1,
                             const float* __restrict__ bv1,
                             const float* __restrict__ wv2,
                             const float* __restrict__ bv2,
                             float* __restrict__ outv) {
    __shared__ float gs[128];
    __shared__ float red[128];
    int b = blockIdx.x, t = threadIdx.x;
    gs[t] = g_pool[b * 128 + t];
    __syncthreads();
    float acc = bv1[t];
#pragma unroll 8
    for (int k = 0; k < 128; k++) acc += gs[k] * wv1[k * 128 + t];
    acc = fmaxf(acc, 0.f) * wv2[t];
    red[t] = acc;
    __syncthreads();
    for (int st = 64; st; st >>= 1) {
        if (t < st) red[t] += red[t + st];
        __syncthreads();
    }
    if (t == 0) outv[b] = red[0] + bv2[0];
}

// ---------------- launch ----------------------------------------------------
extern "C" void kernel_launch(void* const* d_in, const int* in_sizes, int n_in,
                              void* d_out, int out_size) {
    if (n_in < 20) return;
    const float* x  = (const float*)d_in[0];
    const int*   ei = (const int*)d_in[1];
    // the 18 weight/bias tensors are always the LAST 18 inputs
    int base = n_in - 18;
    const float* w_g1 = (const float*)d_in[base + 0];
    const float* b_g1 = (const float*)d_in[base + 1];
    const float* w_g2 = (const float*)d_in[base + 2];
    const float* b_g2 = (const float*)d_in[base + 3];
    const float* w_g3 = (const float*)d_in[base + 4];
    const float* b_g3 = (const float*)d_in[base + 5];
    const float* wn1  = (const float*)d_in[base + 6];
    const float* bn1  = (const float*)d_in[base + 7];
    const float* wn2  = (const float*)d_in[base + 8];
    const float* bn2  = (const float*)d_in[base + 9];
    const float* we1  = (const float*)d_in[base + 10];
    const float* be1  = (const float*)d_in[base + 11];
    const float* we2  = (const float*)d_in[base + 12];
    const float* be2  = (const float*)d_in[base + 13];
    const float* wv1  = (const float*)d_in[base + 14];
    const float* bv1  = (const float*)d_in[base + 15];
    const float* wv2  = (const float*)d_in[base + 16];
    const float* bv2  = (const float*)d_in[base + 17];
    float* out = (float*)d_out;

    void *pA, *pH, *pP, *pQ, *pDeg;
    cudaGetSymbolAddress(&pA, g_bufA);
    cudaGetSymbolAddress(&pH, g_bufH);
    cudaGetSymbolAddress(&pP, g_P);
    cudaGetSymbolAddress(&pQ, g_Q);
    cudaGetSymbolAddress(&pDeg, g_deg);
    float* bufA = (float*)pA;
    float* bufH = (float*)pH;
    float* P = (float*)pP;
    float* Q = (float*)pQ;

    // dynamic smem opt-in
    const int smem128 = (128 * 132 + 128 * 128) * 4;  // 133120
    const int smem64  = (64 * 132 + 64 * 128) * 4;    // 66560
    cudaFuncSetAttribute(gemm_kernel<64, 0>, cudaFuncAttributeMaxDynamicSharedMemorySize, smem64);
    cudaFuncSetAttribute(gemm_kernel<128, 0>, cudaFuncAttributeMaxDynamicSharedMemorySize, smem128);
    cudaFuncSetAttribute(gemm_kernel<128, 1>, cudaFuncAttributeMaxDynamicSharedMemorySize, smem128);
    cudaFuncSetAttribute(gemm_kernel<128, 2>, cudaFuncAttributeMaxDynamicSharedMemorySize, smem128);
    cudaFuncSetAttribute(gemm_kernel<128, 3>, cudaFuncAttributeMaxDynamicSharedMemorySize, smem128);

    // CSR build (reused by all 3 GCN layers)
    cudaMemsetAsync(pDeg, 0, NN * sizeof(int));
    hist_kernel<<<EE / 256, 256>>>(ei);
    scan_kernel<<<1, 1024>>>();
    scatter_kernel<<<EE / 256, 256>>>(ei);

    const int GB = NN / 128;  // 256 GEMM blocks

    // GCN layer 1 (K=64)
    gemm_kernel<64, 0><<<GB, 256, smem64>>>(x, w_g1, nullptr, nullptr, nullptr, bufA);
    agg_kernel<<<NN / 8, 256>>>(bufA, b_g1, bufH);
    // layer 2
    gemm_kernel<128, 0><<<GB, 256, smem128>>>(bufH, w_g2, nullptr, nullptr, nullptr, bufA);
    agg_kernel<<<NN / 8, 256>>>(bufA, b_g2, bufH);
    // layer 3
    gemm_kernel<128, 0><<<GB, 256, smem128>>>(bufH, w_g3, nullptr, nullptr, nullptr, bufA);
    agg_kernel<<<NN / 8, 256>>>(bufA, b_g3, bufH);  // final h in bufH

    // edge head precompute: P = h@we1[:128] + be1 ; Q = h@we1[128:]
    gemm_kernel<128, 1><<<GB, 256, smem128>>>(bufH, we1, be1, nullptr, nullptr, P);
    gemm_kernel<128, 2><<<GB, 256, smem128>>>(bufH, we1 + 128 * 128, nullptr, nullptr, nullptr, Q);

    // node head (fused 2-layer MLP -> logits[:, 0:2048])
    gemm_kernel<128, 3><<<GB, 256, smem128>>>(bufH, wn1, bn1, wn2, bn2, out);

    // edge head -> logits[:, 2048:18432]
    edge_kernel<<<EE / 8, 256>>>(ei, we2, be2, out);

    // value head -> out[B*MAXA : B*MAXA+B]
    pool_kernel<<<BG, 128>>>(bufH);
    value_kernel<<<BG, 128>>>(wv1, bv1, wv2, bv2, out + (size_t)BG * MAXA);
}

// round 10
// speedup vs baseline: 1.1996x; 1.1996x over previous
#include <cuda_runtime.h>

// Problem constants (fixed by setup_inputs)
#define NN    32768      // total nodes (64 * 512)
#define EE    524288     // total edges (64 * 8192)
#define BG    64         // graphs
#define NPER  512
#define EPER  8192
#define MAXA  18432      // 512*4 + 8192*2
#define EMB   128

// ---------------- scratch (device globals; no allocation allowed) ----------
__device__ float g_bufA[NN * EMB];   // GEMM outputs (pre-aggregation, inv-scaled)
__device__ float g_bufH[NN * EMB];   // post-aggregation h
__device__ float g_P[NN * EMB];      // h @ we1_top + be1
__device__ float g_Q[NN * EMB];      // h @ we1_bot
__device__ int   g_deg[NN];
__device__ int   g_off[NN + 1];
__device__ int   g_cur[NN];
__device__ int   g_col[EE];
__device__ float g_inv[NN];          // rsqrt(deg+1)
__device__ float g_pool[BG * EMB];

// ---------------- f32x2 helpers (packed fp32 FMA — 2x FFMA throughput) -----
__device__ __forceinline__ unsigned long long dup2(float a) {
    unsigned long long r;
    unsigned int ai = __float_as_uint(a);
    asm("mov.b64 %0, {%1, %1};" : "=l"(r) : "r"(ai));
    return r;
}
__device__ __forceinline__ void fma2(unsigned long long& c, unsigned long long a,
                                     unsigned long long b) {
    asm("fma.rn.f32x2 %0, %1, %2, %0;" : "+l"(c) : "l"(a), "l"(b));
}
__device__ __forceinline__ float2 unpack2(unsigned long long v) {
    unsigned int lo, hi;
    asm("mov.b64 {%0, %1}, %2;" : "=r"(lo), "=r"(hi) : "l"(v));
    return make_float2(__uint_as_float(lo), __uint_as_float(hi));
}

// ---------------- CSR build ------------------------------------------------
__global__ void hist_kernel(const int* __restrict__ ei) {
    int e = blockIdx.x * blockDim.x + threadIdx.x;
    if (e < EE) atomicAdd(&g_deg[ei[EE + e]], 1);
}

// single-block exclusive scan of g_deg (32768 values), + inv + cursor init
__global__ void scan_kernel() {
    __shared__ int s[1024];
    int t = threadIdx.x;
    int base = t * 32;
    int loc[32];
    int sum = 0;
#pragma unroll
    for (int i = 0; i < 32; i++) { loc[i] = g_deg[base + i]; sum += loc[i]; }
    s[t] = sum;
    __syncthreads();
    for (int d = 1; d < 1024; d <<= 1) {
        int tmp = (t >= d) ? s[t - d] : 0;
        __syncthreads();
        if (t >= d) s[t] += tmp;
        __syncthreads();
    }
    int run = s[t] - sum;  // exclusive prefix
#pragma unroll
    for (int i = 0; i < 32; i++) {
        g_off[base + i] = run;
        g_cur[base + i] = run;
        g_inv[base + i] = rsqrtf((float)(loc[i] + 1));  // +1 self loop
        run += loc[i];
    }
    if (t == 1023) g_off[NN] = s[1023];
}

__global__ void scatter_kernel(const int* __restrict__ ei) {
    int e = blockIdx.x * blockDim.x + threadIdx.x;
    if (e < EE) {
        int d = ei[EE + e];
        int p = atomicAdd(&g_cur[d], 1);
        g_col[p] = ei[e];
    }
}

// ---------------- GEMM: C[M=32768, 128] = A[M,K] @ B[K,128] ----------------
// K processed in chunks of 64 so smem = 66.5 KB -> 2 CTAs/SM (16 warps/SM,
// grid 256 in ONE wave at occ 2).
// EPI 0: C = acc * g_inv[row]         (GCN layer pre-scale)
// EPI 1: C = acc + bias[col]          (P head, be1 folded)
// EPI 2: C = acc                      (Q head)
// EPI 3: node head fused: t = relu(acc + bias); logits = t @ w2 + b2 -> C=d_out
template <int K, int EPI>
__global__ void __launch_bounds__(256, 2)
gemm_kernel(const float* __restrict__ A, const float* __restrict__ Bm,
            const float* __restrict__ bias, const float* __restrict__ w2,
            const float* __restrict__ b2, float* __restrict__ C) {
    extern __shared__ float smem[];
    float* As = smem;             // [64][132]  (transposed A chunk, padded)
    float* Bs = smem + 64 * 132;  // [64][128]

    const int tid = threadIdx.x;
    const int m0 = blockIdx.x * 128;

    const int tm = tid & 31;   // row quad: rows tm*4 .. tm*4+3
    const int tn = tid >> 5;   // col group: cols tn*4 + 32*q + c

    unsigned long long acc[4][4][2];
#pragma unroll
    for (int r = 0; r < 4; r++)
#pragma unroll
        for (int q = 0; q < 4; q++) { acc[r][q][0] = 0ull; acc[r][q][1] = 0ull; }

#pragma unroll
    for (int c = 0; c < K / 64; c++) {
        if (c > 0) __syncthreads();  // protect smem from previous chunk's readers
        // load A chunk (transpose into As[k][m]): rows m0..m0+127, cols c*64..+64
        const float4* A4 =
            reinterpret_cast<const float4*>(A + (size_t)m0 * K + c * 64);
        for (int i = tid; i < 128 * 16; i += 256) {
            int row = i >> 4, kq = i & 15;
            float4 v = A4[row * (K / 4) + kq];
            As[(kq * 4 + 0) * 132 + row] = v.x;
            As[(kq * 4 + 1) * 132 + row] = v.y;
            As[(kq * 4 + 2) * 132 + row] = v.z;
            As[(kq * 4 + 3) * 132 + row] = v.w;
        }
        // load B chunk (row-major copy of rows c*64..+64)
        const float4* B4 = reinterpret_cast<const float4*>(Bm + c * 64 * 128);
        for (int i = tid; i < 64 * 32; i += 256)
            reinterpret_cast<float4*>(Bs)[i] = B4[i];
        __syncthreads();

#pragma unroll 4
        for (int k = 0; k < 64; k++) {
            float4 av = *reinterpret_cast<const float4*>(&As[k * 132 + tm * 4]);
            unsigned long long a0 = dup2(av.x), a1 = dup2(av.y),
                               a2 = dup2(av.z), a3 = dup2(av.w);
#pragma unroll
            for (int q = 0; q < 4; q++) {
                ulonglong2 b = *reinterpret_cast<const ulonglong2*>(
                    &Bs[k * 128 + tn * 4 + 32 * q]);
                fma2(acc[0][q][0], a0, b.x); fma2(acc[0][q][1], a0, b.y);
                fma2(acc[1][q][0], a1, b.x); fma2(acc[1][q][1], a1, b.y);
                fma2(acc[2][q][0], a2, b.x); fma2(acc[2][q][1], a2, b.y);
                fma2(acc[3][q][0], a3, b.x); fma2(acc[3][q][1], a3, b.y);
            }
        }
    }

    if constexpr (EPI == 3) __syncthreads();  // about to reuse smem as Ts

    float* Ts = smem;  // [n][m] transposed hidden tile, stride 130 (EPI==3)
                       // max idx 127*130+127 = 16637 < 16640 floats avail

#pragma unroll
    for (int r = 0; r < 4; r++) {
        int mr = tm * 4 + r;
        int m = m0 + mr;
        float sc = 1.0f;
        if constexpr (EPI == 0) sc = g_inv[m];
#pragma unroll
        for (int q = 0; q < 4; q++) {
            int n0 = tn * 4 + 32 * q;
            float2 lo = unpack2(acc[r][q][0]);
            float2 hi = unpack2(acc[r][q][1]);
            float4 o = make_float4(lo.x, lo.y, hi.x, hi.y);
            if constexpr (EPI == 0) {
                o.x *= sc; o.y *= sc; o.z *= sc; o.w *= sc;
            }
            if constexpr (EPI == 1 || EPI == 3) {
                float4 bb = __ldg(&reinterpret_cast<const float4*>(bias)[tn + 8 * q]);
                o.x += bb.x; o.y += bb.y; o.z += bb.z; o.w += bb.w;
            }
            if constexpr (EPI == 3) {
                // relu, store transposed into Ts[n][m]
                Ts[(n0 + 0) * 130 + mr] = fmaxf(o.x, 0.f);
                Ts[(n0 + 1) * 130 + mr] = fmaxf(o.y, 0.f);
                Ts[(n0 + 2) * 130 + mr] = fmaxf(o.z, 0.f);
                Ts[(n0 + 3) * 130 + mr] = fmaxf(o.w, 0.f);
            } else {
                *reinterpret_cast<float4*>(&C[(size_t)m * 128 + n0]) = o;
            }
        }
    }

    if constexpr (EPI == 3) {
        __syncthreads();
        // stage 2: node_logits = t @ wn2 [128,4] + bn2, scatter into d_out
        int row = tid >> 1;          // local row 0..127
        int jj = (tid & 1) * 2;      // output pair {0,1} or {2,3}
        float s0 = 0.f, s1 = 0.f;
        const float4* W4 = reinterpret_cast<const float4*>(w2);
#pragma unroll 8
        for (int k = 0; k < 128; k++) {
            float tv = Ts[k * 130 + row];
            float4 w = __ldg(&W4[k]);  // (w[k][0..3])
            float wa = jj ? w.z : w.x;
            float wb = jj ? w.w : w.y;
            s0 += tv * wa;
            s1 += tv * wb;
        }
        int gm = m0 + row;
        int b = gm >> 9;
        int ln = gm & 511;
        float2 o2 = make_float2(s0 + b2[jj], s1 + b2[jj + 1]);
        *reinterpret_cast<float2*>(&C[(size_t)b * MAXA + ln * 4 + jj]) = o2;
    }
}

// ---------------- GCN aggregation: warp per dst node -----------------------
// h[d] = relu( inv[d] * (sum_{s in in(d)} a[s] + a[d]) + bias )
// Unrolled x2 with two independent accumulators -> 2 gathers in flight.
__global__ void agg_kernel(const float* __restrict__ a,
                           const float* __restrict__ bias,
                           float* __restrict__ h) {
    int wid = (blockIdx.x * blockDim.x + threadIdx.x) >> 5;
    int lane = threadIdx.x & 31;
    if (wid >= NN) return;
    const float4* A4 = reinterpret_cast<const float4*>(a);
    float4 acc = A4[wid * 32 + lane];  // self (a[d])
    float4 acc2 = make_float4(0.f, 0.f, 0.f, 0.f);
    int j0 = g_off[wid], j1 = g_off[wid + 1];
    int j = j0;
    for (; j + 2 <= j1; j += 2) {
        int s0 = g_col[j];
        int s1 = g_col[j + 1];
        float4 v0 = A4[s0 * 32 + lane];
        float4 v1 = A4[s1 * 32 + lane];
        acc.x += v0.x;  acc.y += v0.y;  acc.z += v0.z;  acc.w += v0.w;
        acc2.x += v1.x; acc2.y += v1.y; acc2.z += v1.z; acc2.w += v1.w;
    }
    if (j < j1) {
        int s = g_col[j];
        float4 v = A4[s * 32 + lane];
        acc.x += v.x; acc.y += v.y; acc.z += v.z; acc.w += v.w;
    }
    acc.x += acc2.x; acc.y += acc2.y; acc.z += acc2.z; acc.w += acc2.w;
    float sc = g_inv[wid];
    float4 bv = __ldg(&reinterpret_cast<const float4*>(bias)[lane]);
    float4 o;
    o.x = fmaxf(acc.x * sc + bv.x, 0.f);
    o.y = fmaxf(acc.y * sc + bv.y, 0.f);
    o.z = fmaxf(acc.z * sc + bv.z, 0.f);
    o.w = fmaxf(acc.w * sc + bv.w, 0.f);
    reinterpret_cast<float4*>(h)[wid * 32 + lane] = o;
}

// ---------------- edge head: warp per TWO consecutive edges ----------------
// Edges 2w, 2w+1 are always in the same graph (8192 edges/graph, even), and
// their outputs are 4 consecutive floats -> one float4 store. 4 gathers in
// flight per warp (2x MLP vs 1-edge version).
__global__ void edge_kernel(const int* __restrict__ ei,
                            const float* __restrict__ we2,
                            const float* __restrict__ be2,
                            float* __restrict__ out) {
    int wid = (blockIdx.x * blockDim.x + threadIdx.x) >> 5;
    int lane = threadIdx.x & 31;
    if (wid >= EE / 2) return;
    int e0 = wid * 2;
    int e1 = e0 + 1;
    int s0i = ei[e0], d0i = ei[EE + e0];
    int s1i = ei[e1], d1i = ei[EE + e1];
    const float4* P4 = reinterpret_cast<const float4*>(g_P);
    const float4* Q4 = reinterpret_cast<const float4*>(g_Q);
    float4 p0 = P4[s0i * 32 + lane];
    float4 q0 = Q4[d0i * 32 + lane];
    float4 p1 = P4[s1i * 32 + lane];
    float4 q1 = Q4[d1i * 32 + lane];

    const float4* W = reinterpret_cast<const float4*>(we2);  // [128][2] rows paired
    float4 w0 = __ldg(&W[lane * 2]);      // rows 4l, 4l+1
    float4 w1 = __ldg(&W[lane * 2 + 1]);  // rows 4l+2, 4l+3

    float a0 = fmaxf(p0.x + q0.x, 0.f), a1 = fmaxf(p0.y + q0.y, 0.f);
    float a2 = fmaxf(p0.z + q0.z, 0.f), a3 = fmaxf(p0.w + q0.w, 0.f);
    float b0 = fmaxf(p1.x + q1.x, 0.f), b1 = fmaxf(p1.y + q1.y, 0.f);
    float b2v = fmaxf(p1.z + q1.z, 0.f), b3 = fmaxf(p1.w + q1.w, 0.f);

    float sA0 = a0 * w0.x + a1 * w0.z + a2 * w1.x + a3 * w1.z;
    float sA1 = a0 * w0.y + a1 * w0.w + a2 * w1.y + a3 * w1.w;
    float sB0 = b0 * w0.x + b1 * w0.z + b2v * w1.x + b3 * w1.z;
    float sB1 = b0 * w0.y + b1 * w0.w + b2v * w1.y + b3 * w1.w;
#pragma unroll
    for (int o = 16; o; o >>= 1) {
        sA0 += __shfl_xor_sync(0xffffffffu, sA0, o);
        sA1 += __shfl_xor_sync(0xffffffffu, sA1, o);
        sB0 += __shfl_xor_sync(0xffffffffu, sB0, o);
        sB1 += __shfl_xor_sync(0xffffffffu, sB1, o);
    }
    if (lane == 0) {
        int b = e0 >> 13;        // edge graph = e / 8192
        int le = e0 & 8191;      // local edge (even)
        float be0 = be2[0], be1 = be2[1];
        float4 o4 = make_float4(sA0 + be0, sA1 + be1, sB0 + be0, sB1 + be1);
        *reinterpret_cast<float4*>(&out[(size_t)b * MAXA + 2048 + le * 2]) = o4;
    }
}

// ---------------- pooling + value head -------------------------------------
__global__ void pool_kernel(const float* __restrict__ h) {
    int b = blockIdx.x, f = threadIdx.x;  // 128 threads
    float s = 0.f;
    const float* base = h + (size_t)b * NPER * EMB + f;
#pragma unroll 8
    for (int r = 0; r < NPER; r++) s += base[r * EMB];
    g_pool[b * EMB + f] = s * (1.0f / (float)NPER);
}

__global__ void value_kernel(const float* __restrict__ wv1,
                             const float* __restrict__ bv1,
                             const float* __restrict__ wv2,
                             const float* __restrict__ bv2,
                             float* __restrict__ outv) {
    __shared__ float gs[128];
    __shared__ float red[128];
    int b = blockIdx.x, t = threadIdx.x;
    gs[t] = g_pool[b * 128 + t];
    __syncthreads();
    float acc = bv1[t];
#pragma unroll 8
    for (int k = 0; k < 128; k++) acc += gs[k] * wv1[k * 128 + t];
    acc = fmaxf(acc, 0.f) * wv2[t];
    red[t] = acc;
    __syncthreads();
    for (int st = 64; st; st >>= 1) {
        if (t < st) red[t] += red[t + st];
        __syncthreads();
    }
    if (t == 0) outv[b] = red[0] + bv2[0];
}

// ---------------- launch ----------------------------------------------------
extern "C" void kernel_launch(void* const* d_in, const int* in_sizes, int n_in,
                              void* d_out, int out_size) {
    if (n_in < 20) return;
    const float* x  = (const float*)d_in[0];
    const int*   ei = (const int*)d_in[1];
    // the 18 weight/bias tensors are always the LAST 18 inputs
    int base = n_in - 18;
    const float* w_g1 = (const float*)d_in[base + 0];
    const float* b_g1 = (const float*)d_in[base + 1];
    const float* w_g2 = (const float*)d_in[base + 2];
    const float* b_g2 = (const float*)d_in[base + 3];
    const float* w_g3 = (const float*)d_in[base + 4];
    const float* b_g3 = (const float*)d_in[base + 5];
    const float* wn1  = (const float*)d_in[base + 6];
    const float* bn1  = (const float*)d_in[base + 7];
    const float* wn2  = (const float*)d_in[base + 8];
    const float* bn2  = (const float*)d_in[base + 9];
    const float* we1  = (const float*)d_in[base + 10];
    const float* be1  = (const float*)d_in[base + 11];
    const float* we2  = (const float*)d_in[base + 12];
    const float* be2  = (const float*)d_in[base + 13];
    const float* wv1  = (const float*)d_in[base + 14];
    const float* bv1  = (const float*)d_in[base + 15];
    const float* wv2  = (const float*)d_in[base + 16];
    const float* bv2  = (const float*)d_in[base + 17];
    float* out = (float*)d_out;

    void *pA, *pH, *pP, *pQ, *pDeg;
    cudaGetSymbolAddress(&pA, g_bufA);
    cudaGetSymbolAddress(&pH, g_bufH);
    cudaGetSymbolAddress(&pP, g_P);
    cudaGetSymbolAddress(&pQ, g_Q);
    cudaGetSymbolAddress(&pDeg, g_deg);
    float* bufA = (float*)pA;
    float* bufH = (float*)pH;
    float* P = (float*)pP;
    float* Q = (float*)pQ;

    // dynamic smem opt-in: (64*132 + 64*128)*4 = 66560 B -> 2 CTAs/SM
    const int smemB = (64 * 132 + 64 * 128) * 4;
    cudaFuncSetAttribute(gemm_kernel<64, 0>, cudaFuncAttributeMaxDynamicSharedMemorySize, smemB);
    cudaFuncSetAttribute(gemm_kernel<128, 0>, cudaFuncAttributeMaxDynamicSharedMemorySize, smemB);
    cudaFuncSetAttribute(gemm_kernel<128, 1>, cudaFuncAttributeMaxDynamicSharedMemorySize, smemB);
    cudaFuncSetAttribute(gemm_kernel<128, 2>, cudaFuncAttributeMaxDynamicSharedMemorySize, smemB);
    cudaFuncSetAttribute(gemm_kernel<128, 3>, cudaFuncAttributeMaxDynamicSharedMemorySize, smemB);

    // CSR build (reused by all 3 GCN layers)
    cudaMemsetAsync(pDeg, 0, NN * sizeof(int));
    hist_kernel<<<EE / 256, 256>>>(ei);
    scan_kernel<<<1, 1024>>>();
    scatter_kernel<<<EE / 256, 256>>>(ei);

    const int GB = NN / 128;  // 256 GEMM blocks -> 1 wave at occ 2

    // GCN layer 1 (K=64)
    gemm_kernel<64, 0><<<GB, 256, smemB>>>(x, w_g1, nullptr, nullptr, nullptr, bufA);
    agg_kernel<<<NN / 8, 256>>>(bufA, b_g1, bufH);
    // layer 2
    gemm_kernel<128, 0><<<GB, 256, smemB>>>(bufH, w_g2, nullptr, nullptr, nullptr, bufA);
    agg_kernel<<<NN / 8, 256>>>(bufA, b_g2, bufH);
    // layer 3
    gemm_kernel<128, 0><<<GB, 256, smemB>>>(bufH, w_g3, nullptr, nullptr, nullptr, bufA);
    agg_kernel<<<NN / 8, 256>>>(bufA, b_g3, bufH);  // final h in bufH

    // edge head precompute: P = h@we1[:128] + be1 ; Q = h@we1[128:]
    gemm_kernel<128, 1><<<GB, 256, smemB>>>(bufH, we1, be1, nullptr, nullptr, P);
    gemm_kernel<128, 2><<<GB, 256, smemB>>>(bufH, we1 + 128 * 128, nullptr, nullptr, nullptr, Q);

    // node head (fused 2-layer MLP -> logits[:, 0:2048])
    gemm_kernel<128, 3><<<GB, 256, smemB>>>(bufH, wn1, bn1, wn2, bn2, out);

    // edge head -> logits[:, 2048:18432]  (2 edges per warp)
    edge_kernel<<<EE / 16, 256>>>(ei, we2, be2, out);

    // value head -> out[B*MAXA : B*MAXA+B]
    pool_kernel<<<BG, 128>>>(bufH);
    value_kernel<<<BG, 128>>>(wv1, bv1, wv2, bv2, out + (size_t)BG * MAXA);
}